// round 12
// baseline (speedup 1.0000x reference)
#include <cuda_runtime.h>
#include <math.h>

// LSTM: S=512, B=64, I=H=1024, fp32.
//  Phase 1: gates_x = x @ W_ih^T + b_ih + b_hh   (one GEMM, packed FFMA2)
//  Phase 2: ONE persistent kernel, 128 CTAs x 256 threads, runs all 512 steps.
//   vs R8 (SMEM-crossbar-bound + lock-step-barrier-bound):
//    - LDS.128 (2 k-pairs per load) in the GEMV inner loop: W loads become
//      8x16B = 128B full-crossbar-utilization transactions -> fma-bound.
//    - NO global lock-step barrier: per-chunk, per-thread waits on exactly the
//      one producer CTA whose h-columns that thread stages. CTAs pipeline
//      freely across steps (monotonic per-CTA flags, per-t h buffers).
//    - 8 k-chunks of 128, double-buffered SMEM staging with register
//      prefetch: L2 load latency hidden behind compute of the previous chunk.
//
// Output layout: [0,S*B*H) output; then h_last [B*H]; then c_last [B*H].

typedef unsigned long long u64;

#define SEQ 512
#define BATCH 64
#define HID 1024
#define G4 4096
#define BH (BATCH * HID)
#define NCTA 128

// scratch (allocation-free rule: __device__ globals)
__device__ float g_gx[(size_t)SEQ * BATCH * G4];     // precomputed input gates
__device__ volatile unsigned int g_arrive[NCTA];     // per-CTA step flags

static __device__ __forceinline__ void ffma2(u64 &d, u64 a, u64 b) {
    asm volatile("fma.rn.f32x2 %0, %1, %2, %0;" : "+l"(d) : "l"(a), "l"(b));
}
static __device__ __forceinline__ u64 pack2(float x, float y) {
    u64 r; asm("mov.b64 %0, {%1, %2};" : "=l"(r) : "f"(x), "f"(y)); return r;
}
static __device__ __forceinline__ float hadd2(u64 v) {
    float x, y; asm("mov.b64 {%0, %1}, %2;" : "=f"(x), "=f"(y) : "l"(v));
    return x + y;
}

__global__ void init_bar() {
    if (threadIdx.x < NCTA) g_arrive[threadIdx.x] = 0u;
}

// ---------------------------------------------------------------------------
// Phase 1 GEMM: C[m][n] = sum_k X[m][k] * Wih[n][k] + (bih[n] + bhh[n])
// M=32768, N=4096, K=1024. BM=BN=128, BK=16, 512 threads, 8m x 4n per thread.
// (unchanged — at its FFMA2 floor)
// ---------------------------------------------------------------------------
__global__ __launch_bounds__(512, 1)
void gemm_gates_x(const float* __restrict__ X, const float* __restrict__ W,
                  const float* __restrict__ bih, const float* __restrict__ bhh)
{
    __shared__ u64 As[2][8][129];
    __shared__ u64 Bs[2][8][129];

    const int t  = threadIdx.x;
    const int n0 = blockIdx.x * 128;
    const int m0 = blockIdx.y * 128;

    const int lrow = t >> 2;
    const int lq   = t & 3;
    const float* ap = X + (size_t)(m0 + lrow) * 1024 + lq * 4;
    const float* bp = W + (size_t)(n0 + lrow) * 1024 + lq * 4;

    const int tn = t & 31;
    const int tm = t >> 5;

    u64 acc[8][4];
#pragma unroll
    for (int i = 0; i < 8; i++)
#pragma unroll
        for (int jj = 0; jj < 4; jj++) acc[i][jj] = 0ull;

    float4 av = *(const float4*)ap;
    float4 bv = *(const float4*)bp;
    As[0][lq * 2][lrow]     = pack2(av.x, av.y);
    As[0][lq * 2 + 1][lrow] = pack2(av.z, av.w);
    Bs[0][lq * 2][lrow]     = pack2(bv.x, bv.y);
    Bs[0][lq * 2 + 1][lrow] = pack2(bv.z, bv.w);
    __syncthreads();

    int buf = 0;
    for (int kt = 0; kt < 64; kt++) {
        if (kt < 63) {
            av = *(const float4*)(ap + (kt + 1) * 16);
            bv = *(const float4*)(bp + (kt + 1) * 16);
        }
#pragma unroll
        for (int q = 0; q < 8; q++) {
            u64 a8[8], b4[4];
#pragma unroll
            for (int i = 0; i < 8; i++) a8[i] = As[buf][q][tm * 8 + i];
#pragma unroll
            for (int jj = 0; jj < 4; jj++) b4[jj] = Bs[buf][q][tn + 32 * jj];
#pragma unroll
            for (int i = 0; i < 8; i++)
#pragma unroll
                for (int jj = 0; jj < 4; jj++) ffma2(acc[i][jj], a8[i], b4[jj]);
        }
        if (kt < 63) {
            As[buf ^ 1][lq * 2][lrow]     = pack2(av.x, av.y);
            As[buf ^ 1][lq * 2 + 1][lrow] = pack2(av.z, av.w);
            Bs[buf ^ 1][lq * 2][lrow]     = pack2(bv.x, bv.y);
            Bs[buf ^ 1][lq * 2 + 1][lrow] = pack2(bv.z, bv.w);
            __syncthreads();
            buf ^= 1;
        }
    }

#pragma unroll
    for (int jj = 0; jj < 4; jj++) {
        const int n = n0 + tn + 32 * jj;
        const float bias = bih[n] + bhh[n];
#pragma unroll
        for (int i = 0; i < 8; i++) {
            const int m = m0 + tm * 8 + i;
            g_gx[(size_t)m * G4 + n] = hadd2(acc[i][jj]) + bias;
        }
    }
}

// ---------------------------------------------------------------------------
// Phase 2: persistent recurrent kernel.
// SMEM: ws[32][514] u64 (131,584B; even stride keeps 16B alignment, j*257
//       mod 8 spreads the 8 j-rows over all 8 16B-bank-groups -> LDS.128
//       conflict-free) + hs[2][64][66] u64 (67,584B, double-buffered h
//       chunks of 128 k). Total 199,168 B -> 1 CTA/SM, 128 CTAs co-resident.
// Thread map: j = tid&7 (hidden col within CTA's 8), bq = tid>>3 -> 2 batches.
// Staging map: thread loads 4 consecutive h columns (kbase + (tid&31)*4 ..+3)
// for 8 batch rows -> those columns come from exactly one producer CTA:
// p = ck*16 + ((tid&31)>>1). Each thread polls only p's flag.
// ---------------------------------------------------------------------------
#define WS_STRIDE 514
#define HS_STRIDE 66
#define WS_U64 (32 * WS_STRIDE)
#define STEP_SMEM ((WS_U64 + 2 * 64 * HS_STRIDE) * 8)

__global__ __launch_bounds__(256, 1)
void lstm_persist(const float* __restrict__ h0, const float* __restrict__ c0,
                  const float* __restrict__ Whh, float* __restrict__ out)
{
    extern __shared__ u64 sm[];
    u64 (*ws)[WS_STRIDE] = (u64(*)[WS_STRIDE])sm;   // [32 W rows][512 kp + pad]
    u64* hsbase = sm + WS_U64;                      // [2][64][66]

    const int tid = threadIdx.x;
    const int j   = tid & 7;
    const int bq  = tid >> 3;        // 0..31
    const int b0  = bq * 2;
    const int j0  = blockIdx.x * 8;
    const int col = j0 + j;

    // staging coords
    const int scol = tid & 31;                      // column-quad within chunk
    const int srow = tid >> 5;                      // base batch row (stride 8)

    // ---- load this CTA's 32 W_hh rows into SMEM once ----
    for (int idx = tid; idx < 8192; idx += 256) {   // 8192 float4
        const int r  = idx >> 8;
        const int c4 = idx & 255;
        const int grow = (r >> 3) * 1024 + j0 + (r & 7);
        float4 v = *(const float4*)(Whh + (size_t)grow * 1024 + c4 * 4);
        ws[r][c4 * 2]     = pack2(v.x, v.y);
        ws[r][c4 * 2 + 1] = pack2(v.z, v.w);
    }

    // W row pointers for this thread's 4 gates
    const u64* wr0 = &ws[0 * 8 + j][0];
    const u64* wr1 = &ws[1 * 8 + j][0];
    const u64* wr2 = &ws[2 * 8 + j][0];
    const u64* wr3 = &ws[3 * 8 + j][0];

    // ---- cell state lives in registers for the whole run ----
    float creg[2];
    creg[0] = c0[(b0 + 0) * HID + col];
    creg[1] = c0[(b0 + 1) * HID + col];
    __syncthreads();

    for (int t = 0; t < SEQ; t++) {
        // prefetch this step's input-gate values (static data)
        float gx[2][4];
#pragma unroll
        for (int bi = 0; bi < 2; bi++)
#pragma unroll
            for (int g = 0; g < 4; g++)
                gx[bi][g] = g_gx[((size_t)t * BATCH + b0 + bi) * G4 + g * 1024 + col];

        const float* h_in = (t == 0) ? h0 : (out + (size_t)(t - 1) * BH);

        u64 acc[4][2];
#pragma unroll
        for (int g = 0; g < 4; g++) { acc[g][0] = 0ull; acc[g][1] = 0ull; }

        // ---- prologue: wait producer of my columns in chunk 0, stage ----
        {
            if (t > 0) {
                const int p = 0 * 16 + (scol >> 1);
                while (g_arrive[p] < (unsigned)t) { __nanosleep(40); }
                __threadfence();
            }
            const float* src = h_in + scol * 4 + srow * 1024;   // chunk 0
            float4 pf[8];
#pragma unroll
            for (int i = 0; i < 8; i++)
                pf[i] = __ldcg((const float4*)(src + i * 8 * 1024));
            u64* dst = hsbase + (size_t)srow * HS_STRIDE + scol * 2;
#pragma unroll
            for (int i = 0; i < 8; i++)
                *(ulonglong2*)(dst + (size_t)i * 8 * HS_STRIDE) =
                    *(const ulonglong2*)&pf[i];
            __syncthreads();
        }

        for (int ck = 0; ck < 8; ck++) {
            // prefetch chunk ck+1 (wait exactly my producer, then LDG)
            float4 pf[8];
            if (ck < 7) {
                if (t > 0) {
                    const int p = (ck + 1) * 16 + (scol >> 1);
                    while (g_arrive[p] < (unsigned)t) { __nanosleep(40); }
                    __threadfence();
                }
                const float* src = h_in + (ck + 1) * 128 + scol * 4 + srow * 1024;
#pragma unroll
                for (int i = 0; i < 8; i++)
                    pf[i] = __ldcg((const float4*)(src + i * 8 * 1024));
            }

            // compute chunk ck from buffer ck&1 (LDS.128 = 2 k-pairs/load)
            const u64* hb = hsbase + (size_t)(ck & 1) * 64 * HS_STRIDE;
            const u64* hp0 = hb + (size_t)(b0 + 0) * HS_STRIDE;
            const u64* hp1 = hb + (size_t)(b0 + 1) * HS_STRIDE;
            const int ko = ck * 64;
#pragma unroll 4
            for (int k2 = 0; k2 < 32; k2++) {
                ulonglong2 w0 = *(const ulonglong2*)(wr0 + ko + 2 * k2);
                ulonglong2 w1 = *(const ulonglong2*)(wr1 + ko + 2 * k2);
                ulonglong2 w2 = *(const ulonglong2*)(wr2 + ko + 2 * k2);
                ulonglong2 w3 = *(const ulonglong2*)(wr3 + ko + 2 * k2);
                ulonglong2 ha = *(const ulonglong2*)(hp0 + 2 * k2);
                ulonglong2 hbv = *(const ulonglong2*)(hp1 + 2 * k2);
                ffma2(acc[0][0], w0.x, ha.x);  ffma2(acc[0][1], w0.x, hbv.x);
                ffma2(acc[1][0], w1.x, ha.x);  ffma2(acc[1][1], w1.x, hbv.x);
                ffma2(acc[2][0], w2.x, ha.x);  ffma2(acc[2][1], w2.x, hbv.x);
                ffma2(acc[3][0], w3.x, ha.x);  ffma2(acc[3][1], w3.x, hbv.x);
                ffma2(acc[0][0], w0.y, ha.y);  ffma2(acc[0][1], w0.y, hbv.y);
                ffma2(acc[1][0], w1.y, ha.y);  ffma2(acc[1][1], w1.y, hbv.y);
                ffma2(acc[2][0], w2.y, ha.y);  ffma2(acc[2][1], w2.y, hbv.y);
                ffma2(acc[3][0], w3.y, ha.y);  ffma2(acc[3][1], w3.y, hbv.y);
            }

            if (ck < 7) {
                u64* dst = hsbase + (size_t)((ck + 1) & 1) * 64 * HS_STRIDE
                         + (size_t)srow * HS_STRIDE + scol * 2;
#pragma unroll
                for (int i = 0; i < 8; i++)
                    *(ulonglong2*)(dst + (size_t)i * 8 * HS_STRIDE) =
                        *(const ulonglong2*)&pf[i];
                __syncthreads();
            }
        }

        // ---- fused cell update (c in registers, h -> global) ----
#pragma unroll
        for (int bi = 0; bi < 2; bi++) {
            const int b = b0 + bi;
            const float gi = hadd2(acc[0][bi]) + gx[bi][0];
            const float gf = hadd2(acc[1][bi]) + gx[bi][1];
            const float gg = hadd2(acc[2][bi]) + gx[bi][2];
            const float go = hadd2(acc[3][bi]) + gx[bi][3];

            const float ig = 1.0f / (1.0f + expf(-gi));
            const float fg = 1.0f / (1.0f + expf(-gf));
            const float gt = tanhf(gg);
            const float og = 1.0f / (1.0f + expf(-go));

            const float cn = fg * creg[bi] + ig * gt;
            const float hn = og * tanhf(cn);
            creg[bi] = cn;

            out[(size_t)t * BH + b * HID + col] = hn;
            if (t == SEQ - 1) {
                out[(size_t)SEQ * BH + b * HID + col] = hn;        // h_last
                out[(size_t)SEQ * BH + BH + b * HID + col] = cn;   // c_last
            }
        }

        // ---- release: publish h[t] ----
        if (t < SEQ - 1) {
            __threadfence();          // every thread orders its own h stores
            __syncthreads();          // all fences done before flag store
            if (tid == 0) g_arrive[blockIdx.x] = (unsigned)(t + 1);
        }
    }
}

extern "C" void kernel_launch(void* const* d_in, const int* in_sizes, int n_in,
                              void* d_out, int out_size)
{
    const float* x    = (const float*)d_in[0];
    const float* h0   = (const float*)d_in[1];
    const float* c0   = (const float*)d_in[2];
    const float* Wih  = (const float*)d_in[3];
    const float* bih  = (const float*)d_in[4];
    const float* Whh  = (const float*)d_in[5];
    const float* bhh  = (const float*)d_in[6];
    float* out = (float*)d_out;

    cudaFuncSetAttribute(lstm_persist,
                         cudaFuncAttributeMaxDynamicSharedMemorySize, STEP_SMEM);

    init_bar<<<1, NCTA>>>();
    gemm_gates_x<<<dim3(32, 256), 512>>>(x, Wih, bih, bhh);
    lstm_persist<<<NCTA, 256, STEP_SMEM>>>(h0, c0, Whh, out);
}